// round 13
// baseline (speedup 1.0000x reference)
#include <cuda_runtime.h>
#include <cstdint>

// out[i,m,l] = w1[i,0]*t4[i,(m-1)%56,l] + w1[i,1]*t4[i,(m-2)%56,l]
// t4 as GEMM over input channels j (K=64 per conv tap; tap = A row shift):
//   D[r, i'] += Xsel[p = r + tap][j] * w2[ibase+i'][3j+tap]
// D rows 0..55 -> t4[na] (l=r), 64..119 -> t4[nb] (l=r-64).
// TF32 mma.sync m16n8k8. Grid (ihalf=2, m=56) = 112 blocks, 1024 threads.
// Warp pair (w, w+16) splits the 24 k-steps 12/12 (smem reduce), register
// w1-mix epilogue. K-dim is sigma-permuted within 8-groups
// (sigma = [0,2,4,6,1,3,5,7]) so each fragment k-pair (q, q+4) is one LDS.64.

static constexpr int A_W     = 72;     // 8 mod 32 -> LDS.64 frags conflict-free
static constexpr int A_ROWS  = 132;
static constexpr int OFF_B_W = A_ROWS * A_W;              // 9504
static constexpr int B_ROWS  = 96;                        // 3 taps x 32 channels
static constexpr int OFF_R_W = OFF_B_W + B_ROWS * A_W;    // 16416
static constexpr int RBUF_W  = 16 * 32 * 9;               // 4608 (stride 9: conflict-free)
static constexpr int SMEM_TOTAL = (OFF_R_W + RBUF_W) * 4; // 84096 B

__device__ __forceinline__ uint32_t f2tf32(float v) {
    uint32_t r; asm("cvt.rna.tf32.f32 %0, %1;" : "=r"(r) : "f"(v)); return r;
}
__device__ __forceinline__ void mma_tf32(float* d, const uint32_t* a, const uint32_t* b) {
    asm("mma.sync.aligned.m16n8k8.row.col.f32.tf32.tf32.f32 "
        "{%0,%1,%2,%3}, {%4,%5,%6,%7}, {%8,%9}, {%0,%1,%2,%3};"
        : "+f"(d[0]), "+f"(d[1]), "+f"(d[2]), "+f"(d[3])
        : "r"(a[0]), "r"(a[1]), "r"(a[2]), "r"(a[3]), "r"(b[0]), "r"(b[1]));
}
// sigma(e): position of k-element e within its 8-group
__device__ __forceinline__ int sigma(int e) { return ((e & 3) << 1) | (e >> 2); }

__global__ __launch_bounds__(1024, 1) void tf32_kernel(
    const float* __restrict__ x,
    const float* __restrict__ w1,
    const float* __restrict__ w2,
    float* __restrict__ out) {

    extern __shared__ uint32_t smem[];
    uint32_t* A = smem;                  // [132][72]: A[p][sigma-permuted j]
    uint32_t* B = smem + OFF_B_W;        // [96][72]:  B[tap*32+i'][perm j]
    float*    R = reinterpret_cast<float*>(smem + OFF_R_W);

    const int tid  = threadIdx.x;
    const int wid  = tid >> 5;
    const int lane = tid & 31;

    const int m     = blockIdx.y;
    const int ihalf = blockIdx.x;
    const int ibase = ihalf * 32;
    const int na    = (m + 55) % 56;
    const int nb    = (m + 54) % 56;

    // Warp tile coordinates + w1 preload FIRST (independent LDGs batch early).
    const int g    = lane >> 2;            // 0..7
    const int q    = lane & 3;             // 0..3
    const int mt0  = wid & 3;              // m-tiles (mt0, mt0+4)
    const int nt   = (wid >> 2) & 3;       // n-tile: cols nt*8..nt*8+7
    const int kh   = wid >> 4;             // k-half 0/1
    float w1r[2][2];
#pragma unroll
    for (int e = 0; e < 2; ++e) {
        int c = ibase + nt * 8 + 2 * q + e;
        w1r[e][0] = __ldg(&w1[2 * c]);
        w1r[e][1] = __ldg(&w1[2 * c + 1]);
    }

    // Halo rows {0, 57, 64, 121} zeroed (gap rows feed only discarded D rows).
    if (tid < 288) {
        int r = tid / 72, w = tid - r * 72;
        int row = (r == 0) ? 0 : (r == 1) ? 57 : (r == 2) ? 64 : 121;
        A[row * A_W + w] = 0u;
    }

    // A fill: 896 items = (sel, jg8 in 0..7, l in 0..55); 8 channels/item.
    // 8 LDGs issue as one batch; sigma-reorder in regs -> 2 STS.128.
    if (tid < 896) {
        int sel = tid >= 448;
        int rem = tid - sel * 448;
        int jg8 = rem / 56;
        int l   = rem - jg8 * 56;
        int n   = sel ? nb : na;
        int p   = sel * 64 + 1 + l;
        const float* xp = &x[(jg8 * 8) * 3136 + n * 56 + l];
        uint32_t u[8];
#pragma unroll
        for (int e = 0; e < 8; ++e) u[e] = f2tf32(xp[e * 3136]);
        uint4 v0 = make_uint4(u[0], u[4], u[1], u[5]);   // positions 0..3 hold e=0,4,1,5
        uint4 v1 = make_uint4(u[2], u[6], u[3], u[7]);   // positions 4..7 hold e=2,6,3,7
        *reinterpret_cast<uint4*>(&A[p * A_W + jg8 * 8])     = v0;
        *reinterpret_cast<uint4*>(&A[p * A_W + jg8 * 8 + 4]) = v1;
    }

    // B fill: 1536 float4 items; round 2 goes to the A-idle high threads.
#pragma unroll
    for (int rnd = 0; rnd < 2; ++rnd) {
        int idx = (rnd == 0) ? tid : (tid >= 512 ? tid + 512 : -1);
        if (idx >= 0) {
            int i  = idx / 48;
            int f4 = idx - i * 48;
            float4 v = *reinterpret_cast<const float4*>(&w2[(ibase + i) * 192 + f4 * 4]);
            float vv[4] = {v.x, v.y, v.z, v.w};
#pragma unroll
            for (int e = 0; e < 4; ++e) {
                int jk  = f4 * 4 + e;
                int j   = jk / 3;
                int tap = jk - 3 * j;
                int pos = (j & ~7) | sigma(j & 7);
                B[(tap * 32 + i) * A_W + pos] = f2tf32(vv[e]);
            }
        }
    }

    __syncthreads();

    // ---- Mainloop: 12 k-steps; fragment pairs via LDS.64 ----
    float d[2][4];
#pragma unroll
    for (int h = 0; h < 2; ++h)
#pragma unroll
        for (int c = 0; c < 4; ++c) d[h][c] = 0.0f;

    const int kbase = kh * 12;
#pragma unroll
    for (int s = 0; s < 12; ++s) {
        const int kidx = kbase + s;
        const int tap  = kidx >> 3;
        const int cw   = ((kidx & 7) << 3) + 2 * q;   // word offset of (q, q+4) pair
        uint32_t afr[2][4], bfr[2];
#pragma unroll
        for (int h = 0; h < 2; ++h) {
            const int r0 = (mt0 + 4 * h) * 16 + g + tap;
            uint2 lo = *reinterpret_cast<const uint2*>(&A[r0 * A_W + cw]);
            uint2 hi = *reinterpret_cast<const uint2*>(&A[(r0 + 8) * A_W + cw]);
            afr[h][0] = lo.x; afr[h][1] = hi.x; afr[h][2] = lo.y; afr[h][3] = hi.y;
        }
        {
            uint2 bv = *reinterpret_cast<const uint2*>(&B[(tap * 32 + nt * 8 + g) * A_W + cw]);
            bfr[0] = bv.x; bfr[1] = bv.y;
        }
#pragma unroll
        for (int h = 0; h < 2; ++h)
            mma_tf32(d[h], afr[h], bfr);
    }

    // ---- Pair reduction: kh=1 dumps partials, kh=0 adds ----
    if (kh == 1) {
        float* dst = &R[((wid - 16) * 32 + lane) * 9];
#pragma unroll
        for (int h = 0; h < 2; ++h)
#pragma unroll
            for (int c = 0; c < 4; ++c) dst[h * 4 + c] = d[h][c];
    }
    __syncthreads();

    if (kh == 0) {
        const float* src = &R[(wid * 32 + lane) * 9];
#pragma unroll
        for (int h = 0; h < 2; ++h)
#pragma unroll
            for (int c = 0; c < 4; ++c) d[h][c] += src[h * 4 + c];

        // ---- Register epilogue ----
        const int l1 = mt0 * 16 + g;       // < 56 always
        const int l2 = l1 + 8;             // invalid when mt0 == 3
#pragma unroll
        for (int e = 0; e < 2; ++e) {
            const int c = ibase + nt * 8 + 2 * q + e;
            float* orow = &out[(c * 56 + m) * 56];
            orow[l1] = fmaf(w1r[e][0], d[0][e], w1r[e][1] * d[1][e]);
            if (l2 < 56)
                orow[l2] = fmaf(w1r[e][0], d[0][2 + e], w1r[e][1] * d[1][2 + e]);
        }
    }
}

extern "C" void kernel_launch(void* const* d_in, const int* in_sizes, int n_in,
                              void* d_out, int out_size) {
    const float* x  = (const float*)d_in[0];   // (1,64,56,56)
    const float* w1 = (const float*)d_in[1];   // (64,2)
    const float* w2 = (const float*)d_in[2];   // (64,64,3)
    float* out = (float*)d_out;                // (1,64,56,56)

    cudaFuncSetAttribute(tf32_kernel,
                         cudaFuncAttributeMaxDynamicSharedMemorySize, SMEM_TOTAL);

    dim3 grid(2, 56);
    tf32_kernel<<<grid, 1024, SMEM_TOTAL>>>(x, w1, w2, out);
}

// round 14
// speedup vs baseline: 1.0294x; 1.0294x over previous
#include <cuda_runtime.h>
#include <cstdint>

// out[i,m,l] = w1[i,0]*t4[i,(m-1)%56,l] + w1[i,1]*t4[i,(m-2)%56,l]
// t4 as GEMM over input channels j (K=64 per conv tap; tap = A row shift):
//   D[r, i'] += Xsel[p = r + tap][j] * w2[ibase+i'][3j+tap]
// D rows 0..55 -> t4[na] (l=r), 64..119 -> t4[nb] (l=r-64).
// TF32 mma.sync m16n8k8, single pass.
// Grid (iq=4, m=56) = 224 blocks, 512 threads, TWO blocks per SM
// (__launch_bounds__(512,2)) so one block's barrier/LDG stalls are covered by
// the other block's mainloop. Warp pair (w, w+8) splits the 24 k-steps 12/12.

static constexpr int A_W     = 68;     // words/row; frag bank = (4g+q)%32 -> conflict-free
static constexpr int A_ROWS  = 132;
static constexpr int OFF_B_W = A_ROWS * A_W;              // 8976
static constexpr int B_ROWS  = 48;                        // 3 taps x 16 channels
static constexpr int OFF_R_W = OFF_B_W + B_ROWS * A_W;    // 12240
static constexpr int RBUF_W  = 8 * 32 * 9;                // 2304 (stride 9: conflict-free)
static constexpr int SMEM_TOTAL = (OFF_R_W + RBUF_W) * 4; // 58176 B  (x2 fits an SM)

__device__ __forceinline__ uint32_t f2tf32(float v) {
    uint32_t r; asm("cvt.rna.tf32.f32 %0, %1;" : "=r"(r) : "f"(v)); return r;
}
__device__ __forceinline__ void mma_tf32(float* d, const uint32_t* a, const uint32_t* b) {
    asm("mma.sync.aligned.m16n8k8.row.col.f32.tf32.tf32.f32 "
        "{%0,%1,%2,%3}, {%4,%5,%6,%7}, {%8,%9}, {%0,%1,%2,%3};"
        : "+f"(d[0]), "+f"(d[1]), "+f"(d[2]), "+f"(d[3])
        : "r"(a[0]), "r"(a[1]), "r"(a[2]), "r"(a[3]), "r"(b[0]), "r"(b[1]));
}

__global__ __launch_bounds__(512, 2) void tf32_kernel(
    const float* __restrict__ x,
    const float* __restrict__ w1,
    const float* __restrict__ w2,
    float* __restrict__ out) {

    extern __shared__ uint32_t smem[];
    uint32_t* A = smem;                  // [132][68]: A[p][j]  (tf32 bits)
    uint32_t* B = smem + OFF_B_W;        // [48][68]:  B[tap*16+i'][j]
    float*    R = reinterpret_cast<float*>(smem + OFF_R_W);

    const int tid  = threadIdx.x;
    const int wid  = tid >> 5;
    const int lane = tid & 31;

    const int m     = blockIdx.y;
    const int iq    = blockIdx.x;          // channel quarter
    const int ibase = iq * 16;
    const int na    = (m + 55) % 56;
    const int nb    = (m + 54) % 56;

    // Warp tile coords + w1 preload first (independent LDGs batch early).
    const int g    = lane >> 2;            // 0..7
    const int q    = lane & 3;             // 0..3
    const int mt0  = wid & 3;              // m-tiles (mt0, mt0+4)
    const int nt   = (wid >> 2) & 1;       // n-tile: cols nt*8 .. nt*8+7
    const int kh   = wid >> 3;             // k-half 0/1
    float w1r[2][2];
#pragma unroll
    for (int e = 0; e < 2; ++e) {
        int c = ibase + nt * 8 + 2 * q + e;
        w1r[e][0] = __ldg(&w1[2 * c]);
        w1r[e][1] = __ldg(&w1[2 * c + 1]);
    }

    // Zero halo rows {0, 57, 64, 121} (272 words).
    if (tid < 272) {
        int r = tid / 68, w = tid - r * 68;
        int row = (r == 0) ? 0 : (r == 1) ? 57 : (r == 2) ? 64 : 121;
        A[row * A_W + w] = 0u;
    }

    // Fill A: item = (sel, jg, l); 4 j-consecutive channels -> one STS.128.
#pragma unroll
    for (int it = 0; it < 4; ++it) {
        int idx = it * 512 + tid;              // valid < 1792
        if (idx < 1792) {
            int sel = idx >= 896;
            int rem = idx - sel * 896;
            int jg  = rem / 56;
            int l   = rem - jg * 56;
            int n   = sel ? nb : na;
            int p   = sel * 64 + 1 + l;
            const float* xp = &x[(jg * 4) * 3136 + n * 56 + l];
            uint4 v;
            v.x = f2tf32(xp[0]);
            v.y = f2tf32(xp[3136]);
            v.z = f2tf32(xp[2 * 3136]);
            v.w = f2tf32(xp[3 * 3136]);
            *reinterpret_cast<uint4*>(&A[p * A_W + jg * 4]) = v;
        }
    }

    // Fill B (this quarter's 16 channels) from float4 loads of w2.
#pragma unroll
    for (int it = 0; it < 2; ++it) {
        int idx = it * 512 + tid;              // valid < 768 (16 ch * 48 float4)
        if (idx < 768) {
            int i  = idx / 48;
            int f4 = idx - i * 48;
            float4 v = *reinterpret_cast<const float4*>(&w2[(ibase + i) * 192 + f4 * 4]);
            float vv[4] = {v.x, v.y, v.z, v.w};
#pragma unroll
            for (int e = 0; e < 4; ++e) {
                int jk  = f4 * 4 + e;
                int j   = jk / 3;
                int tap = jk - 3 * j;
                B[(tap * 16 + i) * A_W + j] = f2tf32(vv[e]);
            }
        }
    }

    __syncthreads();

    // ---- Mainloop: 12 k-steps (kidx = kh*12 + s) ----
    float d[2][4];
#pragma unroll
    for (int h = 0; h < 2; ++h)
#pragma unroll
        for (int c = 0; c < 4; ++c) d[h][c] = 0.0f;

    const int kbase = kh * 12;
#pragma unroll
    for (int s = 0; s < 12; ++s) {
        const int kidx = kbase + s;
        const int tap  = kidx >> 3;
        const int kc   = ((kidx & 7) << 3) + q;
        uint32_t afr[2][4], bfr[2];
#pragma unroll
        for (int h = 0; h < 2; ++h) {
            const int r0 = (mt0 + 4 * h) * 16 + g + tap;
            const uint32_t* p = &A[r0 * A_W + kc];
            afr[h][0] = p[0];
            afr[h][1] = p[8 * A_W];
            afr[h][2] = p[4];
            afr[h][3] = p[8 * A_W + 4];
        }
        {
            const uint32_t* p = &B[(tap * 16 + nt * 8 + g) * A_W + kc];
            bfr[0] = p[0];
            bfr[1] = p[4];
        }
#pragma unroll
        for (int h = 0; h < 2; ++h)
            mma_tf32(d[h], afr[h], bfr);
    }

    // ---- Pair reduction: kh=1 dumps partials, kh=0 adds ----
    if (kh == 1) {
        float* dst = &R[((wid - 8) * 32 + lane) * 9];
#pragma unroll
        for (int h = 0; h < 2; ++h)
#pragma unroll
            for (int c = 0; c < 4; ++c) dst[h * 4 + c] = d[h][c];
    }
    __syncthreads();

    if (kh == 0) {
        const float* src = &R[(wid * 32 + lane) * 9];
#pragma unroll
        for (int h = 0; h < 2; ++h)
#pragma unroll
            for (int c = 0; c < 4; ++c) d[h][c] += src[h * 4 + c];

        // ---- Register epilogue ----
        const int l1 = mt0 * 16 + g;       // < 56 always
        const int l2 = l1 + 8;             // invalid when mt0 == 3
#pragma unroll
        for (int e = 0; e < 2; ++e) {
            const int c = ibase + nt * 8 + 2 * q + e;
            float* orow = &out[(c * 56 + m) * 56];
            orow[l1] = fmaf(w1r[e][0], d[0][e], w1r[e][1] * d[1][e]);
            if (l2 < 56)
                orow[l2] = fmaf(w1r[e][0], d[0][2 + e], w1r[e][1] * d[1][2 + e]);
        }
    }
}

extern "C" void kernel_launch(void* const* d_in, const int* in_sizes, int n_in,
                              void* d_out, int out_size) {
    const float* x  = (const float*)d_in[0];   // (1,64,56,56)
    const float* w1 = (const float*)d_in[1];   // (64,2)
    const float* w2 = (const float*)d_in[2];   // (64,64,3)
    float* out = (float*)d_out;                // (1,64,56,56)

    cudaFuncSetAttribute(tf32_kernel,
                         cudaFuncAttributeMaxDynamicSharedMemorySize, SMEM_TOTAL);

    dim3 grid(4, 56);
    tf32_kernel<<<grid, 512, SMEM_TOTAL>>>(x, w1, w2, out);
}